// round 13
// baseline (speedup 1.0000x reference)
#include <cuda_runtime.h>
#include <cuda_fp16.h>
#include <cstdint>

// ---------------- problem constants ----------------
#define T_TOK 8192
#define DIN   4096
#define DOUT  4096
#define CL    256                  // NUM_ADAPTERS * MAX_RANK pages
#define KSEG  (DIN + CL)           // 4352: fp16 row stride (x | xa)
#define BK    32
#define KCH   (KSEG / BK)          // 136 chunks (gemm2)

#define SSTRIDE 40                 // smem row stride in fp16 (80B: conflict-free ldmatrix)
#define ATILE_B (128 * SSTRIDE * 2)       // 10240 B per 128-row tile
#define STAGE_B (2 * ATILE_B)             // 20480 B per gemm2 stage
#define NSTAGE  3
#define DSMEM_B (NSTAGE * STAGE_B)        // 61440 B

// gemm1b (adapter-sorted LoRA-A GEMM): M-tiles of 128 tokens, N=64, K=4096
#define NTILE1   68                        // max padded tiles: 64 + 4
#define KCH1     (DIN / BK)                // 128 chunks
#define B1TILE_B (64 * SSTRIDE * 2)        // 5120 B
#define STAGE1_B (ATILE_B + B1TILE_B)      // 15360 B
#define DSMEM1_B (NSTAGE * STAGE1_B)       // 46080 B

// ---------------- device scratch (no allocs; zero-initialized at load) ----------------
__device__ __half g_A2[(size_t)T_TOK * KSEG];   // row t: [x(4096) | xa(256)] fp16
__device__ __half g_B2[(size_t)DOUT * KSEG];    // row n: [W | BT]
__device__ __half g_B1[(size_t)CL * KSEG];      // row j: [rank-masked Acat | 0(256)]
__device__ int g_order[NTILE1 * 128];           // sorted token slots (-1 = pad)
__device__ int g_cnt[4], g_fill[4], g_off[4];
__device__ int g_tile_adapter[NTILE1];          // adapter per M-tile (-1 = unused)

// ---------------- generic-PTX helpers (sm_80+) ----------------
__device__ __forceinline__ uint32_t smem_u32(const void* p) {
    uint32_t a;
    asm("{ .reg .u64 t; cvta.to.shared.u64 t, %1; cvt.u32.u64 %0, t; }" : "=r"(a) : "l"(p));
    return a;
}
__device__ __forceinline__ void cp_async16(uint32_t saddr, const void* gaddr) {
    asm volatile("cp.async.cg.shared.global [%0], [%1], 16;" :: "r"(saddr), "l"(gaddr));
}
__device__ __forceinline__ void cp_commit() { asm volatile("cp.async.commit_group;"); }
__device__ __forceinline__ void cp_wait1()  { asm volatile("cp.async.wait_group 1;" ::: "memory"); }
__device__ __forceinline__ void cp_wait0()  { asm volatile("cp.async.wait_group 0;" ::: "memory"); }

__device__ __forceinline__ void ldm_x4(uint32_t* r, uint32_t addr) {
    asm volatile("ldmatrix.sync.aligned.m8n8.x4.shared.b16 {%0,%1,%2,%3}, [%4];"
                 : "=r"(r[0]), "=r"(r[1]), "=r"(r[2]), "=r"(r[3]) : "r"(addr));
}
__device__ __forceinline__ void ldm_x2(uint32_t* r, uint32_t addr) {
    asm volatile("ldmatrix.sync.aligned.m8n8.x2.shared.b16 {%0,%1}, [%2];"
                 : "=r"(r[0]), "=r"(r[1]) : "r"(addr));
}
__device__ __forceinline__ void mma16816(float* c, const uint32_t* a, const uint32_t* b) {
    asm volatile(
        "mma.sync.aligned.m16n8k16.row.col.f32.f16.f16.f32 "
        "{%0,%1,%2,%3}, {%4,%5,%6,%7}, {%8,%9}, {%0,%1,%2,%3};"
        : "+f"(c[0]), "+f"(c[1]), "+f"(c[2]), "+f"(c[3])
        : "r"(a[0]), "r"(a[1]), "r"(a[2]), "r"(a[3]), "r"(b[0]), "r"(b[1]));
}

// ---------------- packing kernels (fp32 -> fp16) ----------------
__global__ void pack_x(const float* __restrict__ x) {
    size_t i4 = ((size_t)blockIdx.x * blockDim.x + threadIdx.x) * 4;
    size_t t = i4 / DIN, k = i4 % DIN;
    float4 v = *(const float4*)(x + i4);
    __half* row = g_A2 + t * KSEG;
    *(__half2*)(row + k)     = __floats2half2_rn(v.x, v.y);
    *(__half2*)(row + k + 2) = __floats2half2_rn(v.z, v.w);
}
__global__ void pack_w(const float* __restrict__ w) {
    size_t i4 = ((size_t)blockIdx.x * blockDim.x + threadIdx.x) * 4;
    size_t n = i4 / DIN, k = i4 % DIN;
    float4 v = *(const float4*)(w + i4);
    __half* row = g_B2 + n * KSEG;
    *(__half2*)(row + k)     = __floats2half2_rn(v.x, v.y);
    *(__half2*)(row + k + 2) = __floats2half2_rn(v.z, v.w);
}
__global__ void pack_bt(const float* __restrict__ b_cache, const int* __restrict__ page) {
    size_t idx = (size_t)blockIdx.x * blockDim.x + threadIdx.x;   // DOUT*CL threads
    size_t n = idx / CL, j = idx % CL;
    g_B2[n * KSEG + DIN + j] = __float2half_rn(b_cache[(size_t)page[j] * DOUT + n]);
}
__global__ void pack_b1(const float* __restrict__ a_cache, const int* __restrict__ page,
                        const int* __restrict__ ranks) {
    size_t i4 = ((size_t)blockIdx.x * blockDim.x + threadIdx.x) * 4;
    size_t j = i4 / DIN, k = i4 % DIN;
    int a = (int)(j >> 6), r = (int)(j & 63);
    float am = (r < ranks[a]) ? 1.0f : 0.0f;
    float4 v = *(const float4*)(a_cache + (size_t)page[j] * DIN + k);
    __half* row = g_B1 + j * KSEG;
    *(__half2*)(row + k)     = __floats2half2_rn(am * v.x, am * v.y);
    *(__half2*)(row + k + 2) = __floats2half2_rn(am * v.z, am * v.w);
}

// ---------------- adapter sort (count -> offsets -> scatter) ----------------
__global__ void k_init() {
    int i = blockIdx.x * blockDim.x + threadIdx.x;
    if (i < NTILE1 * 128) g_order[i] = -1;
    if (i < 4) { g_cnt[i] = 0; g_fill[i] = 0; }
}
__global__ void k_count(const int* __restrict__ adapter_ids) {
    int t = blockIdx.x * blockDim.x + threadIdx.x;
    atomicAdd(&g_cnt[adapter_ids[t]], 1);
}
__global__ void k_offsets() {
    int tile = 0;
    for (int a = 0; a < 4; ++a) {
        g_off[a] = tile * 128;
        int tiles = (g_cnt[a] + 127) >> 7;
        for (int q = 0; q < tiles; ++q) g_tile_adapter[tile + q] = a;
        tile += tiles;
    }
    for (; tile < NTILE1; ++tile) g_tile_adapter[tile] = -1;
}
__global__ void k_scatter(const int* __restrict__ adapter_ids) {
    int t = blockIdx.x * blockDim.x + threadIdx.x;
    int a = adapter_ids[t];
    int pos = atomicAdd(&g_fill[a], 1);
    g_order[g_off[a] + pos] = t;
}

// ---------------- gemm1b: xa[tok, a*64..] = x[tok] @ Acat[a*64..]^T ----------------
// Adapter-sorted M-tiles of 128 tokens (gathered rows), N=64 (own adapter only),
// K=4096. Writes fp16 directly into g_A2's xa columns. 8 warps (4x2), warp 32x32.
__global__ __launch_bounds__(256, 2)
void gemm1b()
{
    extern __shared__ char dsm[];
    const int a = g_tile_adapter[blockIdx.x];
    if (a < 0) return;

    const int tid = threadIdx.x, lane = tid & 31, wid = tid >> 5;
    const int wm = wid >> 1, wn = wid & 1;         // 4 x 2 warp grid
    const int slot0 = blockIdx.x * 128;

    // 3 fill units per thread: units 0..511 = A tile (gathered rows), 512..767 = B
    const __half* gp[3];
    uint32_t soff[3];
#pragma unroll
    for (int i = 0; i < 3; ++i) {
        int u = tid + i * 256;
        if (u < 512) {
            int row = u >> 2, un = u & 3;
            int tok = g_order[slot0 + row];
            if (tok < 0) tok = 0;                  // pad rows: harmless read, no write
            gp[i]   = g_A2 + (size_t)tok * KSEG + un * 8;
            soff[i] = (uint32_t)(row * SSTRIDE + un * 8) * 2;
        } else {
            int v = u - 512, row = v >> 2, un = v & 3;
            gp[i]   = g_B1 + (size_t)(a * 64 + row) * KSEG + un * 8;
            soff[i] = ATILE_B + (uint32_t)(row * SSTRIDE + un * 8) * 2;
        }
    }

    const uint32_t dbase = smem_u32(dsm);
    const uint32_t aOff = ((wm * 32 + (lane & 15)) * SSTRIDE + (lane >> 4) * 8) * 2;
    const uint32_t bOff = ATILE_B + ((wn * 32 + (lane & 7)) * SSTRIDE + ((lane >> 3) & 1) * 8) * 2;

    float acc[2][4][4];
#pragma unroll
    for (int mi = 0; mi < 2; ++mi)
#pragma unroll
        for (int ni = 0; ni < 4; ++ni)
#pragma unroll
            for (int q = 0; q < 4; ++q) acc[mi][ni][q] = 0.0f;

    auto issue = [&](int c, int s) {
        const uint32_t st = dbase + (uint32_t)s * STAGE1_B;
        const size_t k0 = (size_t)c * BK;
#pragma unroll
        for (int i = 0; i < 3; ++i) cp_async16(st + soff[i], gp[i] + k0);
        cp_commit();
    };

    issue(0, 0); issue(1, 1);
    int s = 0, s2 = 2;
    for (int c = 0; c < KCH1; ++c) {
        if (c + 2 < KCH1) cp_wait1(); else cp_wait0();
        __syncthreads();
        if (c + 2 < KCH1) issue(c + 2, s2);

        const uint32_t st = dbase + (uint32_t)s * STAGE1_B;
        const uint32_t aB = st + aOff, bB = st + bOff;
#pragma unroll
        for (int ks = 0; ks < 2; ++ks) {
            uint32_t af[2][4], bf[4][2];
#pragma unroll
            for (int mi = 0; mi < 2; ++mi)
                ldm_x4(af[mi], aB + (mi * 16 * SSTRIDE + ks * 16) * 2);
#pragma unroll
            for (int ni = 0; ni < 4; ++ni)
                ldm_x2(bf[ni], bB + (ni * 8 * SSTRIDE + ks * 16) * 2);
#pragma unroll
            for (int mi = 0; mi < 2; ++mi)
#pragma unroll
                for (int ni = 0; ni < 4; ++ni)
                    mma16816(acc[mi][ni], af[mi], bf[ni]);
        }
        s  = (s  == NSTAGE - 1) ? 0 : s  + 1;
        s2 = (s2 == NSTAGE - 1) ? 0 : s2 + 1;
    }

    // epilogue: write fp16 xa (rank mask baked into B1; other adapters' cols stay 0)
    const int trow = lane >> 2, tcol = (lane & 3) * 2;
#pragma unroll
    for (int mi = 0; mi < 2; ++mi) {
        const int sA = slot0 + wm * 32 + mi * 16 + trow;
        const int tokA = g_order[sA], tokB = g_order[sA + 8];
#pragma unroll
        for (int ni = 0; ni < 4; ++ni) {
            const int n = wn * 32 + ni * 8 + tcol;     // 0..63 within adapter block
            if (tokA >= 0)
                *(__half2*)(g_A2 + (size_t)tokA * KSEG + DIN + a * 64 + n) =
                    __floats2half2_rn(acc[mi][ni][0], acc[mi][ni][1]);
            if (tokB >= 0)
                *(__half2*)(g_A2 + (size_t)tokB * KSEG + DIN + a * 64 + n) =
                    __floats2half2_rn(acc[mi][ni][2], acc[mi][ni][3]);
        }
    }
}

// ---------------- gemm2: out = A2 @ B2^T + bias (K=4352, fused LoRA extension) ----
// CTA 128x128, BK=32, 8 warps (2x4), warp tile 64x32, m16n8k16 f16 -> fp32.
__global__ __launch_bounds__(256, 2)
void mma_gemm2(const float* __restrict__ bias, float* __restrict__ C)
{
    extern __shared__ char dsm[];
    const __half* A = g_A2;
    const __half* B = g_B2;

    const int tid  = threadIdx.x;
    const int lane = tid & 31;
    const int wid  = tid >> 5;
    const int wm   = wid >> 2;
    const int wn   = wid & 3;
    const int bm   = blockIdx.y * 128;
    const int bn   = blockIdx.x * 128;

    const int u0 = tid, u1 = tid + 256;
    const int r0 = u0 >> 2, n0u = u0 & 3;
    const int r1 = u1 >> 2, n1u = u1 & 3;

    const __half* Ag0 = A + (size_t)(bm + r0) * KSEG + n0u * 8;
    const __half* Ag1 = A + (size_t)(bm + r1) * KSEG + n1u * 8;
    const __half* Bg0 = B + (size_t)(bn + r0) * KSEG + n0u * 8;
    const __half* Bg1 = B + (size_t)(bn + r1) * KSEG + n1u * 8;

    const uint32_t dbase = smem_u32(dsm);
    const uint32_t offA0 = (r0 * SSTRIDE + n0u * 8) * 2;
    const uint32_t offA1 = (r1 * SSTRIDE + n1u * 8) * 2;
    const uint32_t offB0 = ATILE_B + (r0 * SSTRIDE + n0u * 8) * 2;
    const uint32_t offB1 = ATILE_B + (r1 * SSTRIDE + n1u * 8) * 2;
    const uint32_t aOff = ((wm * 64 + (lane & 15)) * SSTRIDE + (lane >> 4) * 8) * 2;
    const uint32_t bOff = ATILE_B + ((wn * 32 + (lane & 7)) * SSTRIDE + ((lane >> 3) & 1) * 8) * 2;

    float acc[4][4][4];
#pragma unroll
    for (int mi = 0; mi < 4; ++mi)
#pragma unroll
        for (int ni = 0; ni < 4; ++ni)
#pragma unroll
            for (int q = 0; q < 4; ++q) acc[mi][ni][q] = 0.0f;

    auto issue_loads = [&](int c, int s) {
        const uint32_t st = dbase + (uint32_t)s * STAGE_B;
        const size_t k0 = (size_t)c * BK;
        cp_async16(st + offA0, Ag0 + k0);
        cp_async16(st + offA1, Ag1 + k0);
        cp_async16(st + offB0, Bg0 + k0);
        cp_async16(st + offB1, Bg1 + k0);
        cp_commit();
    };

    issue_loads(0, 0);
    issue_loads(1, 1);

    int s = 0, s2 = 2;
    for (int c = 0; c < KCH; ++c) {
        if (c + 2 < KCH) cp_wait1(); else cp_wait0();
        __syncthreads();
        if (c + 2 < KCH) issue_loads(c + 2, s2);

        const uint32_t st = dbase + (uint32_t)s * STAGE_B;
        const uint32_t aB = st + aOff;
        const uint32_t bB = st + bOff;
#pragma unroll
        for (int ks = 0; ks < 2; ++ks) {
            uint32_t a[4][4], b[4][2];
#pragma unroll
            for (int mi = 0; mi < 4; ++mi)
                ldm_x4(a[mi], aB + (mi * 16 * SSTRIDE + ks * 16) * 2);
#pragma unroll
            for (int ni = 0; ni < 4; ++ni)
                ldm_x2(b[ni], bB + (ni * 8 * SSTRIDE + ks * 16) * 2);
#pragma unroll
            for (int mi = 0; mi < 4; ++mi)
#pragma unroll
                for (int ni = 0; ni < 4; ++ni)
                    mma16816(acc[mi][ni], a[mi], b[ni]);
        }
        s  = (s  == NSTAGE - 1) ? 0 : s  + 1;
        s2 = (s2 == NSTAGE - 1) ? 0 : s2 + 1;
    }

    const int trow = lane >> 2, tcol = (lane & 3) * 2;
#pragma unroll
    for (int mi = 0; mi < 4; ++mi) {
        const int mA = bm + wm * 64 + mi * 16 + trow;
        const int mB = mA + 8;
#pragma unroll
        for (int ni = 0; ni < 4; ++ni) {
            const int n = bn + wn * 32 + ni * 8 + tcol;
            const float2 bz = *(const float2*)(bias + n);
            float2 vA = make_float2(acc[mi][ni][0] + bz.x, acc[mi][ni][1] + bz.y);
            float2 vB = make_float2(acc[mi][ni][2] + bz.x, acc[mi][ni][3] + bz.y);
            *(float2*)(C + (size_t)mA * DOUT + n) = vA;
            *(float2*)(C + (size_t)mB * DOUT + n) = vB;
        }
    }
}

// ---------------- launch ----------------
extern "C" void kernel_launch(void* const* d_in, const int* in_sizes, int n_in,
                              void* d_out, int out_size)
{
    const float* x           = (const float*)d_in[0];
    const float* w           = (const float*)d_in[1];
    const float* bias        = (const float*)d_in[2];
    const float* a_cache     = (const float*)d_in[3];
    const float* b_cache     = (const float*)d_in[4];
    const int*   adapter_ids = (const int*)d_in[5];
    const int*   page        = (const int*)d_in[6];
    const int*   ranks       = (const int*)d_in[7];
    float*       out         = (float*)d_out;

    cudaFuncSetAttribute(mma_gemm2, cudaFuncAttributeMaxDynamicSharedMemorySize, DSMEM_B);
    cudaFuncSetAttribute(gemm1b,    cudaFuncAttributeMaxDynamicSharedMemorySize, DSMEM1_B);

    // adapter sort (independent of packs)
    k_init   <<<NTILE1 * 128 / 256, 256>>>();
    k_count  <<<T_TOK / 256, 256>>>(adapter_ids);
    k_offsets<<<1, 1>>>();
    k_scatter<<<T_TOK / 256, 256>>>(adapter_ids);

    // pack operands (fp32 -> fp16, gathers)
    pack_x <<<(T_TOK * DIN) / 4 / 256, 256>>>(x);
    pack_w <<<(DOUT * DIN) / 4 / 256, 256>>>(w);
    pack_bt<<<(DOUT * CL)      / 256, 256>>>(b_cache, page);
    pack_b1<<<(CL * DIN)   / 4 / 256, 256>>>(a_cache, page, ranks);

    // gemm1b: xa (fp16) written directly into g_A2's xa columns
    gemm1b<<<NTILE1, 256, DSMEM1_B>>>();

    // gemm2: out = x @ W^T + xa @ BT^T + bias  (single-pass fp16, K=4352)
    mma_gemm2<<<dim3(DOUT / 128, T_TOK / 128), 256, DSMEM_B>>>(bias, out);
}